// round 15
// baseline (speedup 1.0000x reference)
#include <cuda_runtime.h>
#include <cuda_bf16.h>
#include <cstdint>

#define NTOK  8192
#define HID   5120
#define INTER 20480
#define NEXP  3

// ---------------- scratch (device globals: no allocation allowed) ----------------
__device__ __align__(256) __nv_bfloat16 g_h[(size_t)NTOK * HID];        // rmsnorm out (bf16)
__device__ __align__(256) __nv_bfloat16 g_act[(size_t)NTOK * INTER];    // up+gelu out (bf16)
__device__ __align__(256) __nv_bfloat16 g_upw[(size_t)NEXP * INTER * HID];  // bf16 weights
__device__ __align__(256) __nv_bfloat16 g_dnw[(size_t)NEXP * HID * INTER];
__device__ __align__(256) __nv_bfloat16 g_zero[INTER];                  // stays zero
__device__ int g_eid[NTOK];
__device__ int g_seg[NEXP * NTOK];
__device__ int g_cnt[NEXP];

// ---------------- helpers ----------------
__device__ __forceinline__ uint32_t smem_u32(const void* p) {
    uint32_t a;
    asm("{ .reg .u64 t; cvta.to.shared.u64 t, %1; cvt.u32.u64 %0, t; }" : "=r"(a) : "l"(p));
    return a;
}
__device__ __forceinline__ void cp_async16(uint32_t dst, const void* src) {
    asm volatile("cp.async.cg.shared.global [%0], [%1], 16;" :: "r"(dst), "l"(src));
}
#define CP_COMMIT() asm volatile("cp.async.commit_group;" ::: "memory")
#define CP_WAIT(n)  asm volatile("cp.async.wait_group %0;" :: "n"(n) : "memory")
#define LDS32(v, addr) asm volatile("ld.shared.b32 %0, [%1];" : "=r"(v) : "r"(addr))

__device__ __forceinline__ void mma_bf16(float* d, const uint32_t* a, const uint32_t* b) {
    asm volatile(
        "mma.sync.aligned.m16n8k16.row.col.f32.bf16.bf16.f32 "
        "{%0,%1,%2,%3}, {%4,%5,%6,%7}, {%8,%9}, {%0,%1,%2,%3};"
        : "+f"(d[0]), "+f"(d[1]), "+f"(d[2]), "+f"(d[3])
        : "r"(a[0]), "r"(a[1]), "r"(a[2]), "r"(a[3]), "r"(b[0]), "r"(b[1]));
}

__device__ __forceinline__ float gelu7f(float x) {
    float g = fminf(x, 7.0f);
    return g / (1.0f + __expf(-1.702f * g));
}

// ---------------- kernel A: fp32 -> bf16 weight conversion ----------------
__global__ void __launch_bounds__(256) convert_kernel(
    const float4* __restrict__ src, uint2* __restrict__ dst, size_t nvec4)
{
    size_t stride = (size_t)gridDim.x * blockDim.x;
    for (size_t i = (size_t)blockIdx.x * blockDim.x + threadIdx.x; i < nvec4; i += stride) {
        float4 v = src[i];
        __nv_bfloat162 h01 = __floats2bfloat162_rn(v.x, v.y);
        __nv_bfloat162 h23 = __floats2bfloat162_rn(v.z, v.w);
        uint2 o;
        o.x = *(uint32_t*)&h01;
        o.y = *(uint32_t*)&h23;
        dst[i] = o;
    }
}

// ---------------- kernel 0/1: decode + route ----------------
__global__ void route_kernel(const int* __restrict__ ids) {
    if (threadIdx.x < NEXP) g_cnt[threadIdx.x] = 0;
    __syncthreads();
    for (int i = threadIdx.x; i < NTOK; i += blockDim.x) {
        int e = ids[i];
        if (e < 0) e = 0;
        if (e >= NEXP) e = NEXP - 1;
        g_eid[i] = e;
        int pos = atomicAdd(&g_cnt[e], 1);
        g_seg[e * NTOK + pos] = i;
    }
}

// ---------------- kernel 2: modality RMSNorm (fp32 in, bf16 out) ----------------
__global__ void __launch_bounds__(256) rmsnorm_kernel(
    const float* __restrict__ x, const float* __restrict__ w)
{
    __shared__ float4 row[HID / 4];   // 20 KB
    __shared__ float red[256];
    int t = blockIdx.x;
    const float4* xin = (const float4*)(x + (size_t)t * HID);
    float ss = 0.f;
    for (int i = threadIdx.x; i < HID / 4; i += 256) {
        float4 v = xin[i];
        row[i] = v;
        ss += v.x * v.x + v.y * v.y + v.z * v.z + v.w * v.w;
    }
    red[threadIdx.x] = ss;
    __syncthreads();
    for (int s = 128; s > 0; s >>= 1) {
        if (threadIdx.x < s) red[threadIdx.x] += red[threadIdx.x + s];
        __syncthreads();
    }
    float rms = rsqrtf(red[0] / (float)HID + 1e-6f);
    int e = g_eid[t];
    const float4* wrow = (const float4*)(w + (size_t)e * HID);
    uint2* out = (uint2*)(g_h + (size_t)t * HID);
    for (int i = threadIdx.x; i < HID / 4; i += 256) {
        float4 v = row[i];
        float4 wv = wrow[i];
        __nv_bfloat162 h01 = __floats2bfloat162_rn(v.x * rms * (wv.x + 1.0f),
                                                   v.y * rms * (wv.y + 1.0f));
        __nv_bfloat162 h23 = __floats2bfloat162_rn(v.z * rms * (wv.z + 1.0f),
                                                   v.w * rms * (wv.w + 1.0f));
        uint2 o;
        o.x = *(uint32_t*)&h01;
        o.y = *(uint32_t*)&h23;
        out[i] = o;
    }
}

// ---------------- kernels 3/4: grouped GEMM via mma.sync (HMMA) ----------------
static constexpr int BM = 128;
static constexpr int BN = 64;
static constexpr int BK = 64;
static constexpr uint32_t ASTRIDE = 144;            // padded row stride (bytes)
static constexpr uint32_t A_TILE_B = BM * ASTRIDE;
static constexpr uint32_t B_TILE_B = BN * ASTRIDE;
static constexpr uint32_t STAGE_B = A_TILE_B + B_TILE_B;
static constexpr uint32_t SMEM_DYN = 2 * STAGE_B + 1024;

template <bool UP>
__global__ void __launch_bounds__(256) moe_gemm_kernel(float* __restrict__ out_f32)
{
    constexpr int Kdim = UP ? HID : INTER;
    constexpr int Odim = UP ? INTER : HID;
    constexpr int NT = Kdim / BK;

    const int e = blockIdx.z;
    const int cnt = g_cnt[e];
    const int m0 = blockIdx.x * BM;
    if (m0 >= cnt) return;
    const int n0 = blockIdx.y * BN;

    const __nv_bfloat16* __restrict__ A = UP ? g_h : g_act;
    const __nv_bfloat16* __restrict__ W = UP ? g_upw : g_dnw;
    const __nv_bfloat16* __restrict__ Wb = W + ((size_t)e * Odim + n0) * Kdim;

    extern __shared__ __align__(16) char dyn_smem[];
    uint32_t raw = smem_u32(dyn_smem);
    const uint32_t sbase = (raw + 1023u) & ~1023u;

    __shared__ int tok_sh[BM];
    __shared__ const __nv_bfloat16* arow_sh[BM];

    const int tid = threadIdx.x;
    const int wid = tid >> 5;
    const int lane = tid & 31;
    const int wm = wid & 1;
    const int wn = wid >> 1;
    const int g4 = lane >> 2;
    const int t4 = lane & 3;

    if (tid < BM) {
        int tok = (m0 + tid < cnt) ? g_seg[e * NTOK + m0 + tid] : -1;
        tok_sh[tid] = tok;
        arow_sh[tid] = (tok >= 0) ? (A + (size_t)tok * Kdim) : g_zero;
    }
    __syncthreads();

    const int rgrp = tid >> 3;
    const int cseg = tid & 7;
    auto fill = [&](int kt, int buf) {
        const int k0 = kt * BK;
        const uint32_t abuf = sbase + buf * STAGE_B;
        const uint32_t bbuf = abuf + A_TILE_B;
        #pragma unroll
        for (int s = 0; s < 4; s++) {
            int r = rgrp + s * 32;
            const char* src = (const char*)(arow_sh[r] + k0) + cseg * 16;
            cp_async16(abuf + (uint32_t)r * ASTRIDE + cseg * 16, src);
        }
        #pragma unroll
        for (int s = 0; s < 2; s++) {
            int r = rgrp + s * 32;
            const char* src = (const char*)(Wb + (size_t)r * Kdim + k0) + cseg * 16;
            cp_async16(bbuf + (uint32_t)r * ASTRIDE + cseg * 16, src);
        }
    };

    float acc[4][2][4];
    #pragma unroll
    for (int i = 0; i < 4; i++)
        #pragma unroll
        for (int j = 0; j < 2; j++)
            #pragma unroll
            for (int q = 0; q < 4; q++) acc[i][j][q] = 0.f;

    fill(0, 0);
    CP_COMMIT();

    for (int kt = 0; kt < NT; kt++) {
        const int buf = kt & 1;
        if (kt + 1 < NT) fill(kt + 1, buf ^ 1);
        CP_COMMIT();
        CP_WAIT(1);
        __syncthreads();

        const uint32_t abuf = sbase + buf * STAGE_B;
        const uint32_t bbuf = abuf + A_TILE_B;

        #pragma unroll
        for (int ks = 0; ks < 4; ks++) {
            const uint32_t kbyte = ks * 32;
            uint32_t afr[4][4];
            uint32_t bfr[2][2];
            #pragma unroll
            for (int mi = 0; mi < 4; mi++) {
                uint32_t base = abuf + (uint32_t)(wm * 64 + mi * 16 + g4) * ASTRIDE
                              + kbyte + t4 * 4;
                LDS32(afr[mi][0], base);
                LDS32(afr[mi][1], base + 8 * ASTRIDE);
                LDS32(afr[mi][2], base + 16);
                LDS32(afr[mi][3], base + 8 * ASTRIDE + 16);
            }
            #pragma unroll
            for (int ni = 0; ni < 2; ni++) {
                uint32_t base = bbuf + (uint32_t)(wn * 16 + ni * 8 + g4) * ASTRIDE
                              + kbyte + t4 * 4;
                LDS32(bfr[ni][0], base);
                LDS32(bfr[ni][1], base + 16);
            }
            #pragma unroll
            for (int mi = 0; mi < 4; mi++)
                #pragma unroll
                for (int ni = 0; ni < 2; ni++)
                    mma_bf16(acc[mi][ni], afr[mi], bfr[ni]);
        }
        __syncthreads();
    }

    // -------- epilogue --------
    #pragma unroll
    for (int mi = 0; mi < 4; mi++) {
        #pragma unroll
        for (int h = 0; h < 2; h++) {
            int rloc = wm * 64 + mi * 16 + g4 + h * 8;
            int tok = tok_sh[rloc];
            if (tok < 0) continue;
            #pragma unroll
            for (int ni = 0; ni < 2; ni++) {
                float f0 = acc[mi][ni][h * 2 + 0];
                float f1 = acc[mi][ni][h * 2 + 1];
                if (UP) {
                    // reference: matmul result -> bf16, gelu in fp32, -> bf16
                    f0 = gelu7f(__bfloat162float(__float2bfloat16_rn(f0)));
                    f1 = gelu7f(__bfloat162float(__float2bfloat16_rn(f1)));
                    __nv_bfloat162 h2 = __floats2bfloat162_rn(f0, f1);
                    uint32_t* orow = (uint32_t*)(g_act + (size_t)tok * INTER + n0);
                    orow[(wn * 16 + ni * 8 + t4 * 2) >> 1] = *(uint32_t*)&h2;
                } else {
                    // final output dtype is fp32 holding bf16-rounded values
                    float2 o;
                    o.x = __bfloat162float(__float2bfloat16_rn(f0));
                    o.y = __bfloat162float(__float2bfloat16_rn(f1));
                    float2* orow = (float2*)(out_f32 + (size_t)tok * HID + n0);
                    orow[(wn * 16 + ni * 8 + t4 * 2) >> 1] = o;
                }
            }
        }
    }
}

// ---------------- launch ----------------
extern "C" void kernel_launch(void* const* d_in, const int* in_sizes, int n_in,
                              void* d_out, int out_size) {
    // metadata order (confirmed by R13 DIAG): x, modality_ids, norm_w, up_w, down_w
    // all tensor data is float32; ids are int32.
    const float* x      = (const float*)d_in[0];
    const int*   ids    = (const int*)d_in[1];
    const float* norm_w = (const float*)d_in[2];
    const float* up_w   = (const float*)d_in[3];
    const float* down_w = (const float*)d_in[4];
    float* out = (float*)d_out;

    cudaFuncSetAttribute(moe_gemm_kernel<true>,
                         cudaFuncAttributeMaxDynamicSharedMemorySize, (int)SMEM_DYN);
    cudaFuncSetAttribute(moe_gemm_kernel<false>,
                         cudaFuncAttributeMaxDynamicSharedMemorySize, (int)SMEM_DYN);

    // weight conversion fp32 -> bf16 (values are exactly bf16-representable)
    const size_t WN = (size_t)NEXP * INTER * HID;   // 314,572,800
    {
        __nv_bfloat16* upw_dev = nullptr;
        __nv_bfloat16* dnw_dev = nullptr;
        cudaGetSymbolAddress((void**)&upw_dev, g_upw);
        cudaGetSymbolAddress((void**)&dnw_dev, g_dnw);
        convert_kernel<<<4096, 256>>>((const float4*)up_w,   (uint2*)upw_dev, WN / 4);
        convert_kernel<<<4096, 256>>>((const float4*)down_w, (uint2*)dnw_dev, WN / 4);
    }

    route_kernel<<<1, 256>>>(ids);
    rmsnorm_kernel<<<NTOK, 256>>>(x, norm_w);

    dim3 gup(NTOK / BM, INTER / BN, NEXP);   // 64 x 320 x 3
    moe_gemm_kernel<true><<<gup, 256, SMEM_DYN>>>(nullptr);

    dim3 gdn(NTOK / BM, HID / BN, NEXP);     // 64 x 80 x 3
    moe_gemm_kernel<false><<<gdn, 256, SMEM_DYN>>>(out);
}

// round 16
// speedup vs baseline: 1.6092x; 1.6092x over previous
#include <cuda_runtime.h>
#include <cuda_bf16.h>
#include <cstdint>

#define NTOK  8192
#define HID   5120
#define INTER 20480
#define NEXP  3

// ---------------- scratch (device globals: no allocation allowed) ----------------
__device__ __align__(256) __nv_bfloat16 g_h[(size_t)NTOK * HID];        // rmsnorm out (bf16)
__device__ __align__(256) __nv_bfloat16 g_act[(size_t)NTOK * INTER];    // up+gelu out (bf16)
__device__ __align__(256) __nv_bfloat16 g_upw[(size_t)NEXP * INTER * HID];  // bf16 weights
__device__ __align__(256) __nv_bfloat16 g_dnw[(size_t)NEXP * HID * INTER];
__device__ __align__(256) __nv_bfloat16 g_zero[INTER];                  // stays zero
__device__ int g_eid[NTOK];
__device__ int g_seg[NEXP * NTOK];
__device__ int g_cnt[NEXP];

// ---------------- helpers ----------------
__device__ __forceinline__ uint32_t smem_u32(const void* p) {
    uint32_t a;
    asm("{ .reg .u64 t; cvta.to.shared.u64 t, %1; cvt.u32.u64 %0, t; }" : "=r"(a) : "l"(p));
    return a;
}
#define SWZ128(o) ((o) ^ (((o) >> 3) & 0x70u))

__device__ __forceinline__ void cp_async16(uint32_t dst, const void* src) {
    asm volatile("cp.async.cg.shared.global [%0], [%1], 16;" :: "r"(dst), "l"(src));
}
#define CP_COMMIT() asm volatile("cp.async.commit_group;" ::: "memory")
#define CP_WAIT(n)  asm volatile("cp.async.wait_group %0;" :: "n"(n) : "memory")

#define LDSM_X4(r0, r1, r2, r3, addr) \
    asm volatile("ldmatrix.sync.aligned.m8n8.x4.shared.b16 {%0,%1,%2,%3}, [%4];" \
                 : "=r"(r0), "=r"(r1), "=r"(r2), "=r"(r3) : "r"(addr))

__device__ __forceinline__ void mma_bf16(float* d, const uint32_t* a, const uint32_t* b) {
    asm volatile(
        "mma.sync.aligned.m16n8k16.row.col.f32.bf16.bf16.f32 "
        "{%0,%1,%2,%3}, {%4,%5,%6,%7}, {%8,%9}, {%0,%1,%2,%3};"
        : "+f"(d[0]), "+f"(d[1]), "+f"(d[2]), "+f"(d[3])
        : "r"(a[0]), "r"(a[1]), "r"(a[2]), "r"(a[3]), "r"(b[0]), "r"(b[1]));
}

__device__ __forceinline__ float gelu7f(float x) {
    float g = fminf(x, 7.0f);
    return g / (1.0f + __expf(-1.702f * g));
}

// ---------------- kernel A: fp32 -> bf16 weight conversion ----------------
__global__ void __launch_bounds__(256) convert_kernel(
    const float4* __restrict__ src, uint2* __restrict__ dst, size_t nvec4)
{
    size_t stride = (size_t)gridDim.x * blockDim.x;
    for (size_t i = (size_t)blockIdx.x * blockDim.x + threadIdx.x; i < nvec4; i += stride) {
        float4 v = src[i];
        __nv_bfloat162 h01 = __floats2bfloat162_rn(v.x, v.y);
        __nv_bfloat162 h23 = __floats2bfloat162_rn(v.z, v.w);
        uint2 o;
        o.x = *(uint32_t*)&h01;
        o.y = *(uint32_t*)&h23;
        dst[i] = o;
    }
}

// ---------------- kernel 0/1: decode + route ----------------
__global__ void route_kernel(const int* __restrict__ ids) {
    if (threadIdx.x < NEXP) g_cnt[threadIdx.x] = 0;
    __syncthreads();
    for (int i = threadIdx.x; i < NTOK; i += blockDim.x) {
        int e = ids[i];
        if (e < 0) e = 0;
        if (e >= NEXP) e = NEXP - 1;
        g_eid[i] = e;
        int pos = atomicAdd(&g_cnt[e], 1);
        g_seg[e * NTOK + pos] = i;
    }
}

// ---------------- kernel 2: modality RMSNorm (fp32 in, bf16 out) ----------------
__global__ void __launch_bounds__(256) rmsnorm_kernel(
    const float* __restrict__ x, const float* __restrict__ w)
{
    __shared__ float4 row[HID / 4];   // 20 KB
    __shared__ float red[256];
    int t = blockIdx.x;
    const float4* xin = (const float4*)(x + (size_t)t * HID);
    float ss = 0.f;
    for (int i = threadIdx.x; i < HID / 4; i += 256) {
        float4 v = xin[i];
        row[i] = v;
        ss += v.x * v.x + v.y * v.y + v.z * v.z + v.w * v.w;
    }
    red[threadIdx.x] = ss;
    __syncthreads();
    for (int s = 128; s > 0; s >>= 1) {
        if (threadIdx.x < s) red[threadIdx.x] += red[threadIdx.x + s];
        __syncthreads();
    }
    float rms = rsqrtf(red[0] / (float)HID + 1e-6f);
    int e = g_eid[t];
    const float4* wrow = (const float4*)(w + (size_t)e * HID);
    uint2* out = (uint2*)(g_h + (size_t)t * HID);
    for (int i = threadIdx.x; i < HID / 4; i += 256) {
        float4 v = row[i];
        float4 wv = wrow[i];
        __nv_bfloat162 h01 = __floats2bfloat162_rn(v.x * rms * (wv.x + 1.0f),
                                                   v.y * rms * (wv.y + 1.0f));
        __nv_bfloat162 h23 = __floats2bfloat162_rn(v.z * rms * (wv.z + 1.0f),
                                                   v.w * rms * (wv.w + 1.0f));
        uint2 o;
        o.x = *(uint32_t*)&h01;
        o.y = *(uint32_t*)&h23;
        out[i] = o;
    }
}

// ---------------- kernels 3/4: grouped GEMM (ldmatrix + SW128, BN=128) ----------------
static constexpr int BM = 128;
static constexpr int BN = 128;
static constexpr int BK = 64;                     // 128 B/row, SW128 atom
static constexpr uint32_t TILE_B = BM * 128;      // 16 KB (A or B tile)
static constexpr uint32_t STAGE_B = 2 * TILE_B;   // 32 KB per stage
static constexpr uint32_t SMEM_DYN = 2 * STAGE_B + 1024;

template <bool UP>
__global__ void __launch_bounds__(256, 2) moe_gemm_kernel(float* __restrict__ out_f32)
{
    constexpr int Kdim = UP ? HID : INTER;
    constexpr int Odim = UP ? INTER : HID;
    constexpr int NT = Kdim / BK;

    const int e = blockIdx.z;
    const int cnt = g_cnt[e];
    const int m0 = blockIdx.x * BM;
    if (m0 >= cnt) return;
    const int n0 = blockIdx.y * BN;

    const __nv_bfloat16* __restrict__ A = UP ? g_h : g_act;
    const __nv_bfloat16* __restrict__ W = UP ? g_upw : g_dnw;
    const __nv_bfloat16* __restrict__ Wb = W + ((size_t)e * Odim + n0) * Kdim;

    extern __shared__ __align__(16) char dyn_smem[];
    uint32_t raw = smem_u32(dyn_smem);
    const uint32_t sbase = (raw + 1023u) & ~1023u;

    __shared__ int tok_sh[BM];
    __shared__ const __nv_bfloat16* arow_sh[BM];

    const int tid = threadIdx.x;
    const int wid = tid >> 5;
    const int lane = tid & 31;
    const int wm = wid & 1;        // 2 warps along M (64 rows each)
    const int wn = wid >> 1;       // 4 warps along N (32 cols each)

    if (tid < BM) {
        int tok = (m0 + tid < cnt) ? g_seg[e * NTOK + m0 + tid] : -1;
        tok_sh[tid] = tok;
        arow_sh[tid] = (tok >= 0) ? (A + (size_t)tok * Kdim) : g_zero;
    }
    __syncthreads();

    // -------- async tile fill (SW128 swizzle) --------
    const int rgrp = tid >> 3;    // 0..31 row group
    const int cseg = tid & 7;     // 16B segment within 128B row
    auto fill = [&](int kt, int buf) {
        const int k0 = kt * BK;
        const uint32_t abuf = sbase + buf * STAGE_B;
        const uint32_t bbuf = abuf + TILE_B;
        #pragma unroll
        for (int s = 0; s < 4; s++) {
            int r = rgrp + s * 32;
            const char* src = (const char*)(arow_sh[r] + k0) + cseg * 16;
            cp_async16(abuf + SWZ128((uint32_t)(r * 128 + cseg * 16)), src);
        }
        #pragma unroll
        for (int s = 0; s < 4; s++) {
            int r = rgrp + s * 32;
            const char* src = (const char*)(Wb + (size_t)r * Kdim + k0) + cseg * 16;
            cp_async16(bbuf + SWZ128((uint32_t)(r * 128 + cseg * 16)), src);
        }
    };

    float acc[4][4][4];
    #pragma unroll
    for (int i = 0; i < 4; i++)
        #pragma unroll
        for (int j = 0; j < 4; j++)
            #pragma unroll
            for (int q = 0; q < 4; q++) acc[i][j][q] = 0.f;

    fill(0, 0);
    CP_COMMIT();

    for (int kt = 0; kt < NT; kt++) {
        const int buf = kt & 1;
        if (kt + 1 < NT) fill(kt + 1, buf ^ 1);
        CP_COMMIT();
        CP_WAIT(1);
        __syncthreads();

        const uint32_t abuf = sbase + buf * STAGE_B;
        const uint32_t bbuf = abuf + TILE_B;

        #pragma unroll
        for (int ks = 0; ks < 4; ks++) {
            const int kb = ks * 16;
            uint32_t afr[4][4];
            uint32_t bfr[4][2];
            // A: 4 x (m16 x k16) fragments via ldmatrix.x4
            #pragma unroll
            for (int mi = 0; mi < 4; mi++) {
                int row = wm * 64 + mi * 16 + (lane & 7) + ((lane >> 3) & 1) * 8;
                int col = kb + (lane >> 4) * 8;
                uint32_t ad = abuf + SWZ128((uint32_t)(row * 128 + col * 2));
                LDSM_X4(afr[mi][0], afr[mi][1], afr[mi][2], afr[mi][3], ad);
            }
            // B: 2 x (n16 x k16) ldmatrix.x4 -> 4 n8 fragments
            #pragma unroll
            for (int nb = 0; nb < 2; nb++) {
                int row = wn * 32 + nb * 16 + (lane & 7) + ((lane >> 4) & 1) * 8;
                int col = kb + ((lane >> 3) & 1) * 8;
                uint32_t ad = bbuf + SWZ128((uint32_t)(row * 128 + col * 2));
                LDSM_X4(bfr[nb * 2][0], bfr[nb * 2][1], bfr[nb * 2 + 1][0], bfr[nb * 2 + 1][1], ad);
            }
            #pragma unroll
            for (int mi = 0; mi < 4; mi++)
                #pragma unroll
                for (int ni = 0; ni < 4; ni++)
                    mma_bf16(acc[mi][ni], afr[mi], bfr[ni]);
        }
        __syncthreads();
    }

    // -------- epilogue --------
    const int tq = lane >> 2;      // row within 8
    const int tr = lane & 3;       // col pair
    #pragma unroll
    for (int mi = 0; mi < 4; mi++) {
        #pragma unroll
        for (int h = 0; h < 2; h++) {
            int rloc = wm * 64 + mi * 16 + tq + h * 8;
            int tok = tok_sh[rloc];
            if (tok < 0) continue;
            if (UP) {
                uint32_t* orow = (uint32_t*)(g_act + (size_t)tok * INTER + n0);
                #pragma unroll
                for (int ni = 0; ni < 4; ni++) {
                    float f0 = acc[mi][ni][h * 2 + 0];
                    float f1 = acc[mi][ni][h * 2 + 1];
                    // reference: matmul result -> bf16, gelu in fp32, -> bf16
                    f0 = gelu7f(__bfloat162float(__float2bfloat16_rn(f0)));
                    f1 = gelu7f(__bfloat162float(__float2bfloat16_rn(f1)));
                    __nv_bfloat162 h2 = __floats2bfloat162_rn(f0, f1);
                    orow[(wn * 32 + ni * 8 + tr * 2) >> 1] = *(uint32_t*)&h2;
                }
            } else {
                float2* orow = (float2*)(out_f32 + (size_t)tok * HID + n0);
                #pragma unroll
                for (int ni = 0; ni < 4; ni++) {
                    float2 o;
                    o.x = __bfloat162float(__float2bfloat16_rn(acc[mi][ni][h * 2 + 0]));
                    o.y = __bfloat162float(__float2bfloat16_rn(acc[mi][ni][h * 2 + 1]));
                    orow[(wn * 32 + ni * 8 + tr * 2) >> 1] = o;
                }
            }
        }
    }
}

// ---------------- launch ----------------
extern "C" void kernel_launch(void* const* d_in, const int* in_sizes, int n_in,
                              void* d_out, int out_size) {
    // metadata order (confirmed R13): x, modality_ids, norm_w, up_w, down_w; all fp32, ids int32.
    const float* x      = (const float*)d_in[0];
    const int*   ids    = (const int*)d_in[1];
    const float* norm_w = (const float*)d_in[2];
    const float* up_w   = (const float*)d_in[3];
    const float* down_w = (const float*)d_in[4];
    float* out = (float*)d_out;

    cudaFuncSetAttribute(moe_gemm_kernel<true>,
                         cudaFuncAttributeMaxDynamicSharedMemorySize, (int)SMEM_DYN);
    cudaFuncSetAttribute(moe_gemm_kernel<false>,
                         cudaFuncAttributeMaxDynamicSharedMemorySize, (int)SMEM_DYN);

    const size_t WN = (size_t)NEXP * INTER * HID;   // 314,572,800
    {
        __nv_bfloat16* upw_dev = nullptr;
        __nv_bfloat16* dnw_dev = nullptr;
        cudaGetSymbolAddress((void**)&upw_dev, g_upw);
        cudaGetSymbolAddress((void**)&dnw_dev, g_dnw);
        convert_kernel<<<4096, 256>>>((const float4*)up_w,   (uint2*)upw_dev, WN / 4);
        convert_kernel<<<4096, 256>>>((const float4*)down_w, (uint2*)dnw_dev, WN / 4);
    }

    route_kernel<<<1, 256>>>(ids);
    rmsnorm_kernel<<<NTOK, 256>>>(x, norm_w);

    dim3 gup(NTOK / BM, INTER / BN, NEXP);   // 64 x 160 x 3
    moe_gemm_kernel<true><<<gup, 256, SMEM_DYN>>>(nullptr);

    dim3 gdn(NTOK / BM, HID / BN, NEXP);     // 64 x 40 x 3
    moe_gemm_kernel<false><<<gdn, 256, SMEM_DYN>>>(out);
}